// round 3
// baseline (speedup 1.0000x reference)
#include <cuda_runtime.h>
#include <cstdint>

#define BATCH 8
#define SEQ   2048
#define DIM   1024
#define UDIM  1024

#define BM 128
#define BN 128
#define BK 16
#define NT 256
#define AP 20    // k-major smem tile row stride (16+4): conflict-free frag reads
#define BP 136   // n-major smem tile row stride (128+8): conflict-free frag reads

// ---------------- scratch (no allocations allowed) ----------------
__device__ float g_Wqm[(size_t)DIM * UDIM];            // Wq @ metric
__device__ float g_bqm[UDIM];                          // bq @ metric
__device__ float g_Q[(size_t)BATCH * SEQ * UDIM];
__device__ float g_K[(size_t)BATCH * SEQ * UDIM];
__device__ float g_V[(size_t)BATCH * SEQ * UDIM];
__device__ float g_S[(size_t)BATCH * SEQ * SEQ];       // scores / probs (in place)

// ---------------- helpers ----------------
__device__ __forceinline__ uint32_t f2tf32(float x) {
    uint32_t r;
    asm("cvt.rna.tf32.f32 %0, %1;" : "=r"(r) : "f"(x));
    return r;
}

__device__ __forceinline__ void mma8(float* c, const uint32_t* a, const uint32_t* b) {
    asm("mma.sync.aligned.m16n8k8.row.col.f32.tf32.tf32.f32 "
        "{%0,%1,%2,%3}, {%4,%5,%6,%7}, {%8,%9}, {%0,%1,%2,%3};"
        : "+f"(c[0]), "+f"(c[1]), "+f"(c[2]), "+f"(c[3])
        : "r"(a[0]), "r"(a[1]), "r"(a[2]), "r"(a[3]), "r"(b[0]), "r"(b[1]));
}

// Load a [128 rows x 16 k] tile where global is row-major with k contiguous
// (used for A in all GEMMs, and for B in the NT scores GEMM).
// smem layout Ts[row][k], row stride AP. Coalesced 16B loads.
__device__ __forceinline__ void load_kmajor(uint32_t (*Ts)[AP], const float* G,
                                            int row0, int ldg, int kt, int tid) {
#pragma unroll
    for (int r = 0; r < 2; r++) {
        int f = tid + r * NT;
        int kq = f & 3, m = f >> 2;
        float4 v = *reinterpret_cast<const float4*>(
            G + (long)(row0 + m) * ldg + kt * BK + kq * 4);
        Ts[m][kq * 4 + 0] = f2tf32(v.x);
        Ts[m][kq * 4 + 1] = f2tf32(v.y);
        Ts[m][kq * 4 + 2] = f2tf32(v.z);
        Ts[m][kq * 4 + 3] = f2tf32(v.w);
    }
}

// Load a [16 k x 128 n] tile where global is row-major with n contiguous
// (B operand of NN GEMMs). smem layout Ts[k][n], row stride BP. Coalesced.
__device__ __forceinline__ void load_nmajor(uint32_t (*Ts)[BP], const float* G,
                                            int n0, int ldg, int kt, int tid) {
#pragma unroll
    for (int r = 0; r < 2; r++) {
        int f = tid + r * NT;
        int nq = f & 31, k = f >> 5;
        float4 v = *reinterpret_cast<const float4*>(
            G + (long)(kt * BK + k) * ldg + n0 + nq * 4);
        Ts[k][nq * 4 + 0] = f2tf32(v.x);
        Ts[k][nq * 4 + 1] = f2tf32(v.y);
        Ts[k][nq * 4 + 2] = f2tf32(v.z);
        Ts[k][nq * 4 + 3] = f2tf32(v.w);
    }
}

// ---------------- NN GEMM: C = A[M,K] @ B[K,N] (+ bias), batched ----------------
// causalK != 0 limits k-tiles to k < m0+BM (PV GEMM, lower-triangular A).
__global__ void __launch_bounds__(NT, 2)
gemm_nn(const float* __restrict__ A, const float* __restrict__ B,
        const float* __restrict__ bias, float* __restrict__ C,
        int M, int N, int K, long sA, long sB, long sC, int causalK)
{
    __shared__ uint32_t As[2][BM][AP];
    __shared__ uint32_t Bs[2][BK][BP];

    const float* Ag = A + (long)blockIdx.z * sA;
    const float* Bg = B + (long)blockIdx.z * sB;
    float*       Cg = C + (long)blockIdx.z * sC;

    const int m0 = blockIdx.y * BM;
    const int n0 = blockIdx.x * BN;
    const int tid = threadIdx.x, lane = tid & 31, warp = tid >> 5;
    const int wm0 = (warp >> 1) * 32, wn0 = (warp & 1) * 64;

    int Ktiles = K / BK;
    if (causalK) { int kl = (m0 + BM) / BK; if (kl < Ktiles) Ktiles = kl; }

    float acc[2][8][4];
#pragma unroll
    for (int i = 0; i < 2; i++)
#pragma unroll
        for (int j = 0; j < 8; j++) {
            acc[i][j][0] = 0.f; acc[i][j][1] = 0.f;
            acc[i][j][2] = 0.f; acc[i][j][3] = 0.f;
        }

    load_kmajor(As[0], Ag, m0, K, 0, tid);
    load_nmajor(Bs[0], Bg, n0, N, 0, tid);
    __syncthreads();

    for (int kt = 0; kt < Ktiles; kt++) {
        int buf = kt & 1;
        if (kt + 1 < Ktiles) {
            load_kmajor(As[buf ^ 1], Ag, m0, K, kt + 1, tid);
            load_nmajor(Bs[buf ^ 1], Bg, n0, N, kt + 1, tid);
        }
#pragma unroll
        for (int kk = 0; kk < BK; kk += 8) {
            uint32_t af[2][4];
#pragma unroll
            for (int im = 0; im < 2; im++) {
                int mr = wm0 + im * 16 + (lane >> 2);
                int kc = kk + (lane & 3);
                af[im][0] = As[buf][mr][kc];
                af[im][1] = As[buf][mr + 8][kc];
                af[im][2] = As[buf][mr][kc + 4];
                af[im][3] = As[buf][mr + 8][kc + 4];
            }
#pragma unroll
            for (int in = 0; in < 8; in++) {
                uint32_t bf[2];
                int nc = wn0 + in * 8 + (lane >> 2);
                int kc = kk + (lane & 3);
                bf[0] = Bs[buf][kc][nc];
                bf[1] = Bs[buf][kc + 4][nc];
                mma8(acc[0][in], af[0], bf);
                mma8(acc[1][in], af[1], bf);
            }
        }
        __syncthreads();
    }

#pragma unroll
    for (int im = 0; im < 2; im++)
#pragma unroll
        for (int in = 0; in < 8; in++) {
            int r0 = m0 + wm0 + im * 16 + (lane >> 2);
            int c0 = n0 + wn0 + in * 8 + (lane & 3) * 2;
            float b0 = 0.f, b1 = 0.f;
            if (bias) { b0 = bias[c0]; b1 = bias[c0 + 1]; }
            *reinterpret_cast<float2*>(Cg + (long)r0 * N + c0) =
                make_float2(acc[im][in][0] + b0, acc[im][in][1] + b1);
            *reinterpret_cast<float2*>(Cg + (long)(r0 + 8) * N + c0) =
                make_float2(acc[im][in][2] + b0, acc[im][in][3] + b1);
        }
}

// ---------------- NT causal scores: S[b,i,j] = (Q[b,i,:].K[b,j,:]) * scale ----------------
__global__ void __launch_bounds__(NT, 2)
gemm_nt_scores(const float* __restrict__ Q, const float* __restrict__ Kmat,
               float* __restrict__ S, float scale)
{
    const int m0 = blockIdx.y * BM;
    const int n0 = blockIdx.x * BN;
    if (n0 > m0) return;  // fully-masked tile: never read downstream

    __shared__ uint32_t As[2][BM][AP];
    __shared__ uint32_t Bs[2][BN][AP];

    const float* Ag = Q    + (long)blockIdx.z * SEQ * UDIM;
    const float* Bg = Kmat + (long)blockIdx.z * SEQ * UDIM;
    float*       Cg = S    + (long)blockIdx.z * SEQ * SEQ;

    const int K = UDIM, N = SEQ;
    const int tid = threadIdx.x, lane = tid & 31, warp = tid >> 5;
    const int wm0 = (warp >> 1) * 32, wn0 = (warp & 1) * 64;

    float acc[2][8][4];
#pragma unroll
    for (int i = 0; i < 2; i++)
#pragma unroll
        for (int j = 0; j < 8; j++) {
            acc[i][j][0] = 0.f; acc[i][j][1] = 0.f;
            acc[i][j][2] = 0.f; acc[i][j][3] = 0.f;
        }

    load_kmajor(As[0], Ag, m0, K, 0, tid);
    load_kmajor(Bs[0], Bg, n0, K, 0, tid);
    __syncthreads();

    const int Ktiles = K / BK;
    for (int kt = 0; kt < Ktiles; kt++) {
        int buf = kt & 1;
        if (kt + 1 < Ktiles) {
            load_kmajor(As[buf ^ 1], Ag, m0, K, kt + 1, tid);
            load_kmajor(Bs[buf ^ 1], Bg, n0, K, kt + 1, tid);
        }
#pragma unroll
        for (int kk = 0; kk < BK; kk += 8) {
            uint32_t af[2][4];
#pragma unroll
            for (int im = 0; im < 2; im++) {
                int mr = wm0 + im * 16 + (lane >> 2);
                int kc = kk + (lane & 3);
                af[im][0] = As[buf][mr][kc];
                af[im][1] = As[buf][mr + 8][kc];
                af[im][2] = As[buf][mr][kc + 4];
                af[im][3] = As[buf][mr + 8][kc + 4];
            }
#pragma unroll
            for (int in = 0; in < 8; in++) {
                uint32_t bf[2];
                int nr = wn0 + in * 8 + (lane >> 2);
                int kc = kk + (lane & 3);
                bf[0] = Bs[buf][nr][kc];
                bf[1] = Bs[buf][nr][kc + 4];
                mma8(acc[0][in], af[0], bf);
                mma8(acc[1][in], af[1], bf);
            }
        }
        __syncthreads();
    }

#pragma unroll
    for (int im = 0; im < 2; im++)
#pragma unroll
        for (int in = 0; in < 8; in++) {
            int i0 = m0 + wm0 + im * 16 + (lane >> 2);
            int j0 = n0 + wn0 + in * 8 + (lane & 3) * 2;
            float v0 = (j0     <= i0)     ? acc[im][in][0] * scale : -1e9f;
            float v1 = (j0 + 1 <= i0)     ? acc[im][in][1] * scale : -1e9f;
            float v2 = (j0     <= i0 + 8) ? acc[im][in][2] * scale : -1e9f;
            float v3 = (j0 + 1 <= i0 + 8) ? acc[im][in][3] * scale : -1e9f;
            *reinterpret_cast<float2*>(Cg + (long)i0 * N + j0) = make_float2(v0, v1);
            *reinterpret_cast<float2*>(Cg + (long)(i0 + 8) * N + j0) = make_float2(v2, v3);
        }
}

// ---------------- causal softmax, in place; zero-fills the diagonal band ----------------
__global__ void softmax_causal(float* __restrict__ S)
{
    const int i = blockIdx.x;
    const int b = blockIdx.y;
    float* row = S + ((long)b * SEQ + i) * SEQ;
    const int n = i + 1;           // valid entries j in [0, i]
    const int tid = threadIdx.x;
    __shared__ float red[256];

    float mx = -3.0e38f;
    for (int j = tid; j < n; j += 256) mx = fmaxf(mx, row[j]);
    red[tid] = mx;
    __syncthreads();
    for (int s = 128; s > 0; s >>= 1) {
        if (tid < s) red[tid] = fmaxf(red[tid], red[tid + s]);
        __syncthreads();
    }
    mx = red[0];
    __syncthreads();

    float sum = 0.f;
    for (int j = tid; j < n; j += 256) {
        float e = __expf(row[j] - mx);
        row[j] = e;
        sum += e;
    }
    red[tid] = sum;
    __syncthreads();
    for (int s = 128; s > 0; s >>= 1) {
        if (tid < s) red[tid] += red[tid + s];
        __syncthreads();
    }
    float inv = 1.f / red[0];
    for (int j = tid; j < n; j += 256) row[j] *= inv;

    // zero the remainder of this row's 128-row block tile so the PV GEMM
    // (which caps k at the tile boundary) reads exact zeros there
    const int tileEnd = ((i >> 7) + 1) << 7;
    for (int j = n + tid; j < tileEnd; j += 256) row[j] = 0.f;
}

// ---------------- bqm = bq @ metric (exact fp32; bq happens to be zeros) ----------------
__global__ void bias_metric(const float* __restrict__ bq,
                            const float* __restrict__ metric,
                            float* __restrict__ bqm)
{
    int v = blockIdx.x * blockDim.x + threadIdx.x;
    if (v >= UDIM) return;
    float s = 0.f;
    for (int u = 0; u < UDIM; u++) s = fmaf(bq[u], metric[(long)u * UDIM + v], s);
    bqm[v] = s;
}

// ---------------- launch ----------------
extern "C" void kernel_launch(void* const* d_in, const int* in_sizes, int n_in,
                              void* d_out, int out_size)
{
    (void)in_sizes; (void)n_in; (void)out_size;
    const float* X1     = (const float*)d_in[0];
    const float* X2     = (const float*)d_in[1];
    const float* Wq     = (const float*)d_in[2];
    const float* bq     = (const float*)d_in[3];
    const float* Wk     = (const float*)d_in[4];
    const float* bk     = (const float*)d_in[5];
    const float* Wv     = (const float*)d_in[6];
    const float* bv     = (const float*)d_in[7];
    const float* metric = (const float*)d_in[8];
    float* out = (float*)d_out;

    void* p;
    cudaGetSymbolAddress(&p, g_Wqm); float* dWqm = (float*)p;
    cudaGetSymbolAddress(&p, g_bqm); float* dbqm = (float*)p;
    cudaGetSymbolAddress(&p, g_Q);   float* dQ   = (float*)p;
    cudaGetSymbolAddress(&p, g_K);   float* dK   = (float*)p;
    cudaGetSymbolAddress(&p, g_V);   float* dV   = (float*)p;
    cudaGetSymbolAddress(&p, g_S);   float* dS   = (float*)p;

    const int M = BATCH * SEQ;
    dim3 blk(NT);

    // fold metric into the query projection
    gemm_nn<<<dim3(UDIM / BN, DIM / BM, 1), blk>>>(Wq, metric, nullptr, dWqm,
                                                   DIM, UDIM, UDIM, 0, 0, 0, 0);
    bias_metric<<<UDIM / 256, 256>>>(bq, metric, dbqm);

    // projections
    gemm_nn<<<dim3(UDIM / BN, M / BM, 1), blk>>>(X1, dWqm, dbqm, dQ,
                                                 M, UDIM, DIM, 0, 0, 0, 0);
    gemm_nn<<<dim3(UDIM / BN, M / BM, 1), blk>>>(X2, Wk, bk, dK,
                                                 M, UDIM, DIM, 0, 0, 0, 0);
    gemm_nn<<<dim3(UDIM / BN, M / BM, 1), blk>>>(X2, Wv, bv, dV,
                                                 M, UDIM, DIM, 0, 0, 0, 0);

    // causal attention
    gemm_nt_scores<<<dim3(SEQ / BN, SEQ / BM, BATCH), blk>>>(dQ, dK, dS, 1.0f / 32.0f);
    softmax_causal<<<dim3(SEQ, BATCH), 256>>>(dS);
    gemm_nn<<<dim3(UDIM / BN, SEQ / BM, BATCH), blk>>>(dS, dV, nullptr, out,
                                                       SEQ, UDIM, SEQ,
                                                       (long)SEQ * SEQ,
                                                       (long)SEQ * UDIM,
                                                       (long)SEQ * UDIM, 1);
}

// round 5
// speedup vs baseline: 1.3201x; 1.3201x over previous
#include <cuda_runtime.h>
#include <cstdint>

#define BATCH 8
#define SEQ   2048
#define DIM   1024
#define UDIM  1024

#define BM_ 128          // CTA tile M
#define BN_ 256          // CTA tile N
#define KC  32           // K per stage (32 floats = 128B row)
#define NSTG 3
#define NTH 256
#define STAGE_A 16384    // 128 rows x 128B
#define STAGE_B 32768    // 256 rows x 128B
#define STAGE_BYTES (STAGE_A + STAGE_B)
#define SMEM_BYTES (NSTG * STAGE_BYTES)

// ---------------- scratch (no allocations allowed) ----------------
__device__ float g_metricT[(size_t)DIM*UDIM];
__device__ float g_Wqr[(size_t)DIM*UDIM];
__device__ float g_WqmT[(size_t)DIM*UDIM];
__device__ float g_WkT[(size_t)DIM*UDIM];
__device__ float g_WvT[(size_t)DIM*UDIM];
__device__ float g_bqm[UDIM];
__device__ float g_X1[(size_t)BATCH*SEQ*DIM];
__device__ float g_X2[(size_t)BATCH*SEQ*DIM];
__device__ float g_Q [(size_t)BATCH*SEQ*UDIM];
__device__ float g_Kt[(size_t)BATCH*SEQ*UDIM];
__device__ float g_V [(size_t)BATCH*SEQ*UDIM];
__device__ float g_VT[(size_t)BATCH*SEQ*UDIM];
__device__ float g_S [(size_t)BATCH*SEQ*SEQ];

// ---------------- helpers ----------------
__device__ __forceinline__ float rnd(float x) {         // fp32 -> tf32-representable (rna)
    uint32_t r; asm("cvt.rna.tf32.f32 %0, %1;" : "=r"(r) : "f"(x));
    return __uint_as_float(r);
}
__device__ __forceinline__ uint32_t s2u(const void* p) {
    return (uint32_t)__cvta_generic_to_shared(p);
}
__device__ __forceinline__ void cp16(uint32_t s, const void* g) {
    asm volatile("cp.async.cg.shared.global [%0], [%1], 16;" :: "r"(s), "l"(g) : "memory");
}
__device__ __forceinline__ void cp_commit() {
    asm volatile("cp.async.commit_group;" ::: "memory");
}
__device__ __forceinline__ void cp_wait(int n) {
    if (n <= 0)      asm volatile("cp.async.wait_group 0;" ::: "memory");
    else if (n == 1) asm volatile("cp.async.wait_group 1;" ::: "memory");
    else             asm volatile("cp.async.wait_group 2;" ::: "memory");
}
__device__ __forceinline__ void ldsm4(uint32_t* r, uint32_t a) {
    asm volatile("ldmatrix.sync.aligned.m8n8.x4.shared.b16 {%0,%1,%2,%3}, [%4];"
        : "=r"(r[0]), "=r"(r[1]), "=r"(r[2]), "=r"(r[3]) : "r"(a));
}
__device__ __forceinline__ void mma8(float* c, const uint32_t* a, const uint32_t* b) {
    asm("mma.sync.aligned.m16n8k8.row.col.f32.tf32.tf32.f32 "
        "{%0,%1,%2,%3}, {%4,%5,%6,%7}, {%8,%9}, {%0,%1,%2,%3};"
        : "+f"(c[0]), "+f"(c[1]), "+f"(c[2]), "+f"(c[3])
        : "r"(a[0]), "r"(a[1]), "r"(a[2]), "r"(a[3]), "r"(b[0]), "r"(b[1]));
}
// SW128 swizzle of (row, byte-in-row): byte chunk bits [4:6] XOR row bits [0:2]
__device__ __forceinline__ int swz(int row, int b) {
    return row * 128 + (b ^ ((row * 16) & 0x70));
}

// ---------------- NT GEMM: C[m,n] = scale * sum_k A[m,k]*B[n,k] (+bias) ----------------
// A, B k-major (k contiguous). ldmatrix-fed m16n8k8 tf32 mma, 3-stage cp.async.
__global__ void __launch_bounds__(NTH, 1)
mma_gemm(const float* __restrict__ A, const float* __restrict__ B,
         const float* __restrict__ bias, float* __restrict__ C,
         int N, int K, int ldA, int ldB, int ldC,
         long strA, long strB, long strC,
         float scale, int doRound, int causalK, int causalMask)
{
    const int m0 = blockIdx.y * BM_;
    const int n0 = blockIdx.x * BN_;
    if (causalMask && n0 > m0 + BM_ - 1) return;   // fully-masked scores tile

    extern __shared__ char smem[];
    const uint32_t sbase = s2u(smem);
    const int tid = threadIdx.x, lane = tid & 31, w = tid >> 5;
    const int wm0 = (w >> 2) * 64;                 // 2 warps in m
    const int wn0 = (w & 3) * 64;                  // 4 warps in n

    const float* Ag = A + (size_t)blockIdx.z * strA;
    const float* Bg = B + (size_t)blockIdx.z * strB;
    float*       Cg = C + (size_t)blockIdx.z * strC;

    int Kc = K / KC;
    if (causalK) { int kl = ((m0 + BM_ + 255) & ~255) / KC; if (kl < Kc) Kc = kl; }

    uint32_t stA[NSTG], stB[NSTG];
#pragma unroll
    for (int s = 0; s < NSTG; s++) { stA[s] = sbase + s * STAGE_BYTES; stB[s] = stA[s] + STAGE_A; }

    // ---- cp.async fill: thread -> (row r0 + 32q, 16B chunk b16) ----
    const int r0  = tid >> 3;            // 0..31
    const int b16 = (tid & 7) * 16;
    auto fill = [&](int kc, int s) {
        const char* asrc = (const char*)(Ag + (size_t)(m0 + r0) * ldA + kc * KC) + b16;
        const size_t aStep = (size_t)32 * ldA * 4;
        uint32_t ab = stA[s];
#pragma unroll
        for (int q = 0; q < 4; q++) { cp16(ab + swz(r0 + q * 32, b16), asrc); asrc += aStep; }
        const char* bsrc = (const char*)(Bg + (size_t)(n0 + r0) * ldB + kc * KC) + b16;
        const size_t bStep = (size_t)32 * ldB * 4;
        uint32_t bb = stB[s];
#pragma unroll
        for (int q = 0; q < 8; q++) { cp16(bb + swz(r0 + q * 32, b16), bsrc); bsrc += bStep; }
        cp_commit();
    };

    // ---- per-thread ldmatrix address components ----
    // A frag im (16 rows): lanes 0-7 rows, 8-15 rows+8, 16-23 rows@k+4, 24-31 rows+8@k+4
    int aoff[4], amask[4];
#pragma unroll
    for (int im = 0; im < 4; im++) {
        int row = wm0 + im * 16 + (lane & 7) + ((lane >> 3) & 1) * 8;
        aoff[im] = row * 128; amask[im] = (row * 16) & 0x70;
    }
    const int akb = ((lane >> 4) & 1) * 16;
    // B pair ip (16 n-rows): lanes 0-7 n, 8-15 n@k+4, 16-23 n+8, 24-31 n+8@k+4
    int boff[4], bmask[4];
#pragma unroll
    for (int ip = 0; ip < 4; ip++) {
        int row = wn0 + ip * 16 + (lane & 7) + ((lane >> 4) & 1) * 8;
        boff[ip] = row * 128; bmask[ip] = (row * 16) & 0x70;
    }
    const int bkb = ((lane >> 3) & 1) * 16;

    float acc[4][8][4];
#pragma unroll
    for (int im = 0; im < 4; im++)
#pragma unroll
        for (int in = 0; in < 8; in++) {
            acc[im][in][0] = 0.f; acc[im][in][1] = 0.f;
            acc[im][in][2] = 0.f; acc[im][in][3] = 0.f;
        }

    fill(0, 0); fill(1, 1);

    for (int i = 0; i < Kc; i++) {
        __syncthreads();                                  // prev iter's reads done
        if (i + 2 < Kc) fill(i + 2, (i + 2) % NSTG);
        int pend = Kc - 1 - i; if (pend > 2) pend = 2;
        cp_wait(pend);
        __syncthreads();                                  // stage i visible to all

        const uint32_t sa = stA[i % NSTG], sb = stB[i % NSTG];
#pragma unroll
        for (int ks = 0; ks < 4; ks++) {
            uint32_t af[4][4], bf[4][4];
            const int kbA = ks * 32 + akb, kbB = ks * 32 + bkb;
#pragma unroll
            for (int im = 0; im < 4; im++) ldsm4(af[im], sa + aoff[im] + (kbA ^ amask[im]));
#pragma unroll
            for (int ip = 0; ip < 4; ip++) ldsm4(bf[ip], sb + boff[ip] + (kbB ^ bmask[ip]));
#pragma unroll
            for (int im = 0; im < 4; im++)
#pragma unroll
                for (int in = 0; in < 8; in++)
                    mma8(acc[im][in], af[im], &bf[in >> 1][(in & 1) * 2]);
        }
    }

    // ---- epilogue ----
#pragma unroll
    for (int im = 0; im < 4; im++)
#pragma unroll
        for (int in = 0; in < 8; in++) {
            const int i0 = m0 + wm0 + im * 16 + (lane >> 2);
            const int j0 = n0 + wn0 + in * 8 + (lane & 3) * 2;
            float v0 = acc[im][in][0] * scale, v1 = acc[im][in][1] * scale;
            float v2 = acc[im][in][2] * scale, v3 = acc[im][in][3] * scale;
            if (bias) {
                const float b0 = bias[j0], b1 = bias[j0 + 1];
                v0 += b0; v1 += b1; v2 += b0; v3 += b1;
            }
            if (causalMask) {
                if (j0     > i0)     v0 = -1e9f;
                if (j0 + 1 > i0)     v1 = -1e9f;
                if (j0     > i0 + 8) v2 = -1e9f;
                if (j0 + 1 > i0 + 8) v3 = -1e9f;
            }
            if (doRound) { v0 = rnd(v0); v1 = rnd(v1); v2 = rnd(v2); v3 = rnd(v3); }
            *reinterpret_cast<float2*>(Cg + (size_t)i0 * ldC + j0) = make_float2(v0, v1);
            *reinterpret_cast<float2*>(Cg + (size_t)(i0 + 8) * ldC + j0) = make_float2(v2, v3);
        }
}

// ---------------- aux kernels ----------------
__global__ void round4(const float4* __restrict__ x, float4* __restrict__ y, size_t n4) {
    size_t i = (size_t)blockIdx.x * blockDim.x + threadIdx.x;
    const size_t st = (size_t)gridDim.x * blockDim.x;
    for (; i < n4; i += st) {
        float4 v = x[i];
        v.x = rnd(v.x); v.y = rnd(v.y); v.z = rnd(v.z); v.w = rnd(v.w);
        y[i] = v;
    }
}

// dst[Nc, Mr] = rnd(src[Mr, Nc])^T, batched over z
__global__ void transpose_round(const float* __restrict__ src, float* __restrict__ dst,
                                int Mr, int Nc, long ss, long sd) {
    __shared__ float t[32][33];
    const float* S = src + (size_t)blockIdx.z * ss;
    float*       D = dst + (size_t)blockIdx.z * sd;
    int x = blockIdx.x * 32 + threadIdx.x;
    int y = blockIdx.y * 32 + threadIdx.y;
#pragma unroll
    for (int j = 0; j < 32; j += 8)
        t[threadIdx.y + j][threadIdx.x] = rnd(S[(size_t)(y + j) * Nc + x]);
    __syncthreads();
    x = blockIdx.y * 32 + threadIdx.x;
    y = blockIdx.x * 32 + threadIdx.y;
#pragma unroll
    for (int j = 0; j < 32; j += 8)
        D[(size_t)(y + j) * Mr + x] = t[threadIdx.x][threadIdx.y + j];
}

// causal softmax in place; rounds probs to tf32; zero-fills to 256-boundary
__global__ void softmax_causal(float* __restrict__ S) {
    const int i = blockIdx.x, b = blockIdx.y;
    float* row = S + ((size_t)b * SEQ + i) * SEQ;
    const int n = i + 1;
    const int tid = threadIdx.x;
    __shared__ float red[256];

    float mx = -3.0e38f;
    for (int j = tid; j < n; j += 256) mx = fmaxf(mx, row[j]);
    red[tid] = mx; __syncthreads();
    for (int s = 128; s > 0; s >>= 1) { if (tid < s) red[tid] = fmaxf(red[tid], red[tid + s]); __syncthreads(); }
    mx = red[0]; __syncthreads();

    float sum = 0.f;
    for (int j = tid; j < n; j += 256) { float e = __expf(row[j] - mx); row[j] = e; sum += e; }
    red[tid] = sum; __syncthreads();
    for (int s = 128; s > 0; s >>= 1) { if (tid < s) red[tid] += red[tid + s]; __syncthreads(); }
    const float inv = 1.f / red[0];
    for (int j = tid; j < n; j += 256) row[j] = rnd(row[j] * inv);

    const int tileEnd = ((i >> 8) + 1) << 8;
    for (int j = n + tid; j < tileEnd; j += 256) row[j] = 0.f;
}

__global__ void bias_metric(const float* __restrict__ bq, const float* __restrict__ metric,
                            float* __restrict__ bqm) {
    const int v = blockIdx.x * blockDim.x + threadIdx.x;
    if (v >= UDIM) return;
    float s = 0.f;
    for (int u = 0; u < UDIM; u++) s = fmaf(bq[u], metric[(size_t)u * UDIM + v], s);
    bqm[v] = s;
}

// ---------------- launch ----------------
extern "C" void kernel_launch(void* const* d_in, const int* in_sizes, int n_in,
                              void* d_out, int out_size)
{
    (void)in_sizes; (void)n_in; (void)out_size;
    const float* X1     = (const float*)d_in[0];
    const float* X2     = (const float*)d_in[1];
    const float* Wq     = (const float*)d_in[2];
    const float* bq     = (const float*)d_in[3];
    const float* Wk     = (const float*)d_in[4];
    const float* bk     = (const float*)d_in[5];
    const float* Wv     = (const float*)d_in[6];
    const float* bv     = (const float*)d_in[7];
    const float* metric = (const float*)d_in[8];
    float* out = (float*)d_out;

    cudaFuncSetAttribute(mma_gemm, cudaFuncAttributeMaxDynamicSharedMemorySize, SMEM_BYTES);

    void* p;
    cudaGetSymbolAddress(&p, g_metricT); float* dMT  = (float*)p;
    cudaGetSymbolAddress(&p, g_Wqr);     float* dWqr = (float*)p;
    cudaGetSymbolAddress(&p, g_WqmT);    float* dWqm = (float*)p;
    cudaGetSymbolAddress(&p, g_WkT);     float* dWkT = (float*)p;
    cudaGetSymbolAddress(&p, g_WvT);     float* dWvT = (float*)p;
    cudaGetSymbolAddress(&p, g_bqm);     float* dbqm = (float*)p;
    cudaGetSymbolAddress(&p, g_X1);      float* dX1  = (float*)p;
    cudaGetSymbolAddress(&p, g_X2);      float* dX2  = (float*)p;
    cudaGetSymbolAddress(&p, g_Q);       float* dQ   = (float*)p;
    cudaGetSymbolAddress(&p, g_Kt);      float* dK   = (float*)p;
    cudaGetSymbolAddress(&p, g_V);       float* dV   = (float*)p;
    cudaGetSymbolAddress(&p, g_VT);      float* dVT  = (float*)p;
    cudaGetSymbolAddress(&p, g_S);       float* dS   = (float*)p;

    const int M = BATCH * SEQ;                 // 16384
    dim3 blk(NTH), t8(32, 8);

    // pre-round every GEMM operand to tf32 (HW truncates; pre-round keeps rna semantics)
    round4<<<1024, 256>>>((const float4*)X1, (float4*)dX1, (size_t)M * DIM / 4);
    round4<<<1024, 256>>>((const float4*)X2, (float4*)dX2, (size_t)M * DIM / 4);
    round4<<<256, 256>>>((const float4*)Wq, (float4*)dWqr, (size_t)DIM * UDIM / 4);
    transpose_round<<<dim3(32, 32, 1), t8>>>(metric, dMT, DIM, UDIM, 0, 0);
    transpose_round<<<dim3(32, 32, 1), t8>>>(Wk, dWkT, DIM, UDIM, 0, 0);
    transpose_round<<<dim3(32, 32, 1), t8>>>(Wv, dWvT, DIM, UDIM, 0, 0);
    bias_metric<<<UDIM / 256, 256>>>(bq, metric, dbqm);

    // WqmT[v,d] = sum_u metricT[v,u] * Wq[d,u]  ( = (Wq@metric)^T ), rounded
    mma_gemm<<<dim3(DIM / BN_, UDIM / BM_, 1), blk, SMEM_BYTES>>>(
        dMT, dWqr, nullptr, dWqm, DIM, UDIM, UDIM, UDIM, DIM,
        0, 0, 0, 1.f, 1, 0, 0);

    // projections (NT with transposed weights), outputs rounded
    mma_gemm<<<dim3(UDIM / BN_, M / BM_, 1), blk, SMEM_BYTES>>>(
        dX1, dWqm, dbqm, dQ, UDIM, DIM, DIM, DIM, UDIM, 0, 0, 0, 1.f, 1, 0, 0);
    mma_gemm<<<dim3(UDIM / BN_, M / BM_, 1), blk, SMEM_BYTES>>>(
        dX2, dWkT, bk, dK, UDIM, DIM, DIM, DIM, UDIM, 0, 0, 0, 1.f, 1, 0, 0);
    mma_gemm<<<dim3(UDIM / BN_, M / BM_, 1), blk, SMEM_BYTES>>>(
        dX2, dWvT, bv, dV, UDIM, DIM, DIM, DIM, UDIM, 0, 0, 0, 1.f, 1, 0, 0);

    // causal scores (fully-masked tiles early-return; diagonal tiles masked in epilogue)
    mma_gemm<<<dim3(SEQ / BN_, SEQ / BM_, BATCH), blk, SMEM_BYTES>>>(
        dQ, dK, nullptr, dS, SEQ, UDIM, UDIM, UDIM, SEQ,
        (long)SEQ * UDIM, (long)SEQ * UDIM, (long)SEQ * SEQ,
        1.0f / 32.0f, 0, 0, 1);

    softmax_causal<<<dim3(SEQ, BATCH), 256>>>(dS);

    // V^T per batch for the PV NT GEMM
    transpose_round<<<dim3(32, 64, BATCH), t8>>>(dV, dVT, SEQ, UDIM,
        (long)SEQ * UDIM, (long)SEQ * UDIM);

    // O = P @ V  (k-limited by causality at 256 granularity; final output, no rounding)
    mma_gemm<<<dim3(UDIM / BN_, SEQ / BM_, BATCH), blk, SMEM_BYTES>>>(
        dS, dVT, nullptr, out, UDIM, SEQ, SEQ, SEQ, UDIM,
        (long)SEQ * SEQ, (long)SEQ * UDIM, (long)SEQ * UDIM,
        1.f, 0, 1, 0);
}

// round 7
// speedup vs baseline: 1.4289x; 1.0824x over previous
#include <cuda_runtime.h>
#include <cstdint>

#define BATCH 8
#define SEQ   2048
#define DIM   1024
#define UDIM  1024

#define BM_ 128          // CTA tile M
#define BN_ 128          // CTA tile N
#define KC  32           // K per stage (32 floats = 128B row)
#define NSTG 3
#define NTH 256
#define STAGE_A 16384    // 128 rows x 128B
#define STAGE_B 16384    // 128 rows x 128B
#define STAGE_BYTES (STAGE_A + STAGE_B)
#define SMEM_BYTES (NSTG * STAGE_BYTES)     // 96KB -> 2 CTAs/SM

// ---------------- scratch (no allocations allowed) ----------------
__device__ float g_metricT[(size_t)DIM*UDIM];
__device__ float g_Wqr[(size_t)DIM*UDIM];
__device__ float g_WqmT[(size_t)DIM*UDIM];
__device__ float g_WkT[(size_t)DIM*UDIM];
__device__ float g_WvT[(size_t)DIM*UDIM];
__device__ float g_bqm[UDIM];
__device__ float g_X1[(size_t)BATCH*SEQ*DIM];
__device__ float g_X2[(size_t)BATCH*SEQ*DIM];
__device__ float g_Q [(size_t)BATCH*SEQ*UDIM];
__device__ float g_Kt[(size_t)BATCH*SEQ*UDIM];
__device__ float g_V [(size_t)BATCH*SEQ*UDIM];
__device__ float g_VT[(size_t)BATCH*SEQ*UDIM];
__device__ float g_S [(size_t)BATCH*SEQ*SEQ];

// ---------------- helpers ----------------
__device__ __forceinline__ float rnd(float x) {         // fp32 -> tf32-representable (rna)
    uint32_t r; asm("cvt.rna.tf32.f32 %0, %1;" : "=r"(r) : "f"(x));
    return __uint_as_float(r);
}
__device__ __forceinline__ uint32_t s2u(const void* p) {
    return (uint32_t)__cvta_generic_to_shared(p);
}
__device__ __forceinline__ void cp16(uint32_t s, const void* g) {
    asm volatile("cp.async.cg.shared.global [%0], [%1], 16;" :: "r"(s), "l"(g) : "memory");
}
__device__ __forceinline__ void cp_commit() {
    asm volatile("cp.async.commit_group;" ::: "memory");
}
__device__ __forceinline__ void cp_wait(int n) {
    if (n <= 0)      asm volatile("cp.async.wait_group 0;" ::: "memory");
    else if (n == 1) asm volatile("cp.async.wait_group 1;" ::: "memory");
    else             asm volatile("cp.async.wait_group 2;" ::: "memory");
}
__device__ __forceinline__ void ldsm4(uint32_t* r, uint32_t a) {
    asm volatile("ldmatrix.sync.aligned.m8n8.x4.shared.b16 {%0,%1,%2,%3}, [%4];"
        : "=r"(r[0]), "=r"(r[1]), "=r"(r[2]), "=r"(r[3]) : "r"(a));
}
__device__ __forceinline__ void mma8(float* c, const uint32_t* a, const uint32_t* b) {
    asm("mma.sync.aligned.m16n8k8.row.col.f32.tf32.tf32.f32 "
        "{%0,%1,%2,%3}, {%4,%5,%6,%7}, {%8,%9}, {%0,%1,%2,%3};"
        : "+f"(c[0]), "+f"(c[1]), "+f"(c[2]), "+f"(c[3])
        : "r"(a[0]), "r"(a[1]), "r"(a[2]), "r"(a[3]), "r"(b[0]), "r"(b[1]));
}
// SW128 swizzle of (row, byte-in-row): byte chunk bits [4:6] XOR row bits [0:2]
__device__ __forceinline__ int swz(int row, int b) {
    return row * 128 + (b ^ ((row * 16) & 0x70));
}

// ---------------- NT GEMM: C[m,n] = scale * sum_k A[m,k]*B[n,k] (+bias) ----------------
// A, B k-major (k contiguous). ldmatrix-fed m16n8k8 tf32 mma, 3-stage cp.async.
// CTA 128x128, warp 64x32 (8 warps: 2 in m, 4 in n), 2 CTAs/SM.
__global__ void __launch_bounds__(NTH, 2)
mma_gemm(const float* __restrict__ A, const float* __restrict__ B,
         const float* __restrict__ bias, float* __restrict__ C,
         int N, int K, int ldA, int ldB, int ldC,
         long strA, long strB, long strC,
         float scale, int doRound, int causalK, int causalMask)
{
    const int m0 = blockIdx.y * BM_;
    const int n0 = blockIdx.x * BN_;
    if (causalMask && n0 > m0) return;             // fully-masked scores tile

    extern __shared__ char smem[];
    const uint32_t sbase = s2u(smem);
    const int tid = threadIdx.x, lane = tid & 31, w = tid >> 5;
    const int wm0 = (w >> 2) * 64;                 // 2 warps in m
    const int wn0 = (w & 3) * 32;                  // 4 warps in n

    const float* Ag = A + (size_t)blockIdx.z * strA;
    const float* Bg = B + (size_t)blockIdx.z * strB;
    float*       Cg = C + (size_t)blockIdx.z * strC;

    int Kc = K / KC;
    if (causalK) { int kl = (m0 + BM_) / KC; if (kl < Kc) Kc = kl; }

    uint32_t stA[NSTG], stB[NSTG];
#pragma unroll
    for (int s = 0; s < NSTG; s++) { stA[s] = sbase + s * STAGE_BYTES; stB[s] = stA[s] + STAGE_A; }

    // ---- cp.async fill: thread -> (row r0 + 32q, 16B chunk b16) ----
    const int r0  = tid >> 3;            // 0..31
    const int b16 = (tid & 7) * 16;
    auto fill = [&](int kc, int s) {
        const char* asrc = (const char*)(Ag + (size_t)(m0 + r0) * ldA + kc * KC) + b16;
        const size_t aStep = (size_t)32 * ldA * 4;
        uint32_t ab = stA[s];
#pragma unroll
        for (int q = 0; q < 4; q++) { cp16(ab + swz(r0 + q * 32, b16), asrc); asrc += aStep; }
        const char* bsrc = (const char*)(Bg + (size_t)(n0 + r0) * ldB + kc * KC) + b16;
        const size_t bStep = (size_t)32 * ldB * 4;
        uint32_t bb = stB[s];
#pragma unroll
        for (int q = 0; q < 4; q++) { cp16(bb + swz(r0 + q * 32, b16), bsrc); bsrc += bStep; }
        cp_commit();
    };

    // ---- per-thread ldmatrix address components ----
    // A frag im (16 rows): lanes 0-7 rows, 8-15 rows+8, 16-23 rows@k+4, 24-31 rows+8@k+4
    int aoff[4], amask[4];
#pragma unroll
    for (int im = 0; im < 4; im++) {
        int row = wm0 + im * 16 + (lane & 7) + ((lane >> 3) & 1) * 8;
        aoff[im] = row * 128; amask[im] = (row * 16) & 0x70;
    }
    const int akb = ((lane >> 4) & 1) * 16;
    // B pair ip (16 n-rows): lanes 0-7 n, 8-15 n@k+4, 16-23 n+8, 24-31 n+8@k+4
    int boff[2], bmask[2];
#pragma unroll
    for (int ip = 0; ip < 2; ip++) {
        int row = wn0 + ip * 16 + (lane & 7) + ((lane >> 4) & 1) * 8;
        boff[ip] = row * 128; bmask[ip] = (row * 16) & 0x70;
    }
    const int bkb = ((lane >> 3) & 1) * 16;

    float acc[4][4][4];
#pragma unroll
    for (int im = 0; im < 4; im++)
#pragma unroll
        for (int in = 0; in < 4; in++) {
            acc[im][in][0] = 0.f; acc[im][in][1] = 0.f;
            acc[im][in][2] = 0.f; acc[im][in][3] = 0.f;
        }

    fill(0, 0); fill(1, 1);

    for (int i = 0; i < Kc; i++) {
        __syncthreads();                                  // prev iter's reads done
        if (i + 2 < Kc) fill(i + 2, (i + 2) % NSTG);
        int pend = Kc - 1 - i; if (pend > 2) pend = 2;
        cp_wait(pend);
        __syncthreads();                                  // stage i visible to all

        const uint32_t sa = stA[i % NSTG], sb = stB[i % NSTG];
#pragma unroll
        for (int ks = 0; ks < 4; ks++) {
            uint32_t af[4][4], bf[2][4];
            const int kbA = ks * 32 + akb, kbB = ks * 32 + bkb;
#pragma unroll
            for (int im = 0; im < 4; im++) ldsm4(af[im], sa + aoff[im] + (kbA ^ amask[im]));
#pragma unroll
            for (int ip = 0; ip < 2; ip++) ldsm4(bf[ip], sb + boff[ip] + (kbB ^ bmask[ip]));
#pragma unroll
            for (int im = 0; im < 4; im++)
#pragma unroll
                for (int in = 0; in < 4; in++)
                    mma8(acc[im][in], af[im], &bf[in >> 1][(in & 1) * 2]);
        }
    }

    // ---- epilogue ----
#pragma unroll
    for (int im = 0; im < 4; im++)
#pragma unroll
        for (int in = 0; in < 4; in++) {
            const int i0 = m0 + wm0 + im * 16 + (lane >> 2);
            const int j0 = n0 + wn0 + in * 8 + (lane & 3) * 2;
            float v0 = acc[im][in][0] * scale, v1 = acc[im][in][1] * scale;
            float v2 = acc[im][in][2] * scale, v3 = acc[im][in][3] * scale;
            if (bias) {
                const float b0 = bias[j0], b1 = bias[j0 + 1];
                v0 += b0; v1 += b1; v2 += b0; v3 += b1;
            }
            if (causalMask) {
                if (j0     > i0)     v0 = -1e9f;
                if (j0 + 1 > i0)     v1 = -1e9f;
                if (j0     > i0 + 8) v2 = -1e9f;
                if (j0 + 1 > i0 + 8) v3 = -1e9f;
            }
            if (doRound) { v0 = rnd(v0); v1 = rnd(v1); v2 = rnd(v2); v3 = rnd(v3); }
            *reinterpret_cast<float2*>(Cg + (size_t)i0 * ldC + j0) = make_float2(v0, v1);
            *reinterpret_cast<float2*>(Cg + (size_t)(i0 + 8) * ldC + j0) = make_float2(v2, v3);
        }
}

// ---------------- aux kernels ----------------
__global__ void round4(const float4* __restrict__ x, float4* __restrict__ y, size_t n4) {
    size_t i = (size_t)blockIdx.x * blockDim.x + threadIdx.x;
    const size_t st = (size_t)gridDim.x * blockDim.x;
    for (; i < n4; i += st) {
        float4 v = x[i];
        v.x = rnd(v.x); v.y = rnd(v.y); v.z = rnd(v.z); v.w = rnd(v.w);
        y[i] = v;
    }
}

// dst[Nc, Mr] = rnd(src[Mr, Nc])^T, batched over z
__global__ void transpose_round(const float* __restrict__ src, float* __restrict__ dst,
                                int Mr, int Nc, long ss, long sd) {
    __shared__ float t[32][33];
    const float* S = src + (size_t)blockIdx.z * ss;
    float*       D = dst + (size_t)blockIdx.z * sd;
    int x = blockIdx.x * 32 + threadIdx.x;
    int y = blockIdx.y * 32 + threadIdx.y;
#pragma unroll
    for (int j = 0; j < 32; j += 8)
        t[threadIdx.y + j][threadIdx.x] = rnd(S[(size_t)(y + j) * Nc + x]);
    __syncthreads();
    x = blockIdx.y * 32 + threadIdx.x;
    y = blockIdx.x * 32 + threadIdx.y;
#pragma unroll
    for (int j = 0; j < 32; j += 8)
        D[(size_t)(y + j) * Mr + x] = t[threadIdx.x][threadIdx.y + j];
}

// causal softmax in place; rounds probs to tf32; zero-fills to 128-boundary
__global__ void softmax_causal(float* __restrict__ S) {
    const int i = blockIdx.x, b = blockIdx.y;
    float* row = S + ((size_t)b * SEQ + i) * SEQ;
    const int n = i + 1;
    const int tid = threadIdx.x;
    __shared__ float red[256];

    float mx = -3.0e38f;
    for (int j = tid; j < n; j += 256) mx = fmaxf(mx, row[j]);
    red[tid] = mx; __syncthreads();
    for (int s = 128; s > 0; s >>= 1) { if (tid < s) red[tid] = fmaxf(red[tid], red[tid + s]); __syncthreads(); }
    mx = red[0]; __syncthreads();

    float sum = 0.f;
    for (int j = tid; j < n; j += 256) { float e = __expf(row[j] - mx); row[j] = e; sum += e; }
    red[tid] = sum; __syncthreads();
    for (int s = 128; s > 0; s >>= 1) { if (tid < s) red[tid] += red[tid + s]; __syncthreads(); }
    const float inv = 1.f / red[0];
    for (int j = tid; j < n; j += 256) row[j] = rnd(row[j] * inv);

    const int tileEnd = ((i >> 7) + 1) << 7;
    for (int j = n + tid; j < tileEnd; j += 256) row[j] = 0.f;
}

__global__ void bias_metric(const float* __restrict__ bq, const float* __restrict__ metric,
                            float* __restrict__ bqm) {
    const int v = blockIdx.x * blockDim.x + threadIdx.x;
    if (v >= UDIM) return;
    float s = 0.f;
    for (int u = 0; u < UDIM; u++) s = fmaf(bq[u], metric[(size_t)u * UDIM + v], s);
    bqm[v] = s;
}

// ---------------- launch ----------------
extern "C" void kernel_launch(void* const* d_in, const int* in_sizes, int n_in,
                              void* d_out, int out_size)
{
    (void)in_sizes; (void)n_in; (void)out_size;
    const float* X1     = (const float*)d_in[0];
    const float* X2     = (const float*)d_in[1];
    const float* Wq     = (const float*)d_in[2];
    const float* bq     = (const float*)d_in[3];
    const float* Wk     = (const float*)d_in[4];
    const float* bk     = (const float*)d_in[5];
    const float* Wv     = (const float*)d_in[6];
    const float* bv     = (const float*)d_in[7];
    const float* metric = (const float*)d_in[8];
    float* out = (float*)d_out;

    cudaFuncSetAttribute(mma_gemm, cudaFuncAttributeMaxDynamicSharedMemorySize, SMEM_BYTES);

    void* p;
    cudaGetSymbolAddress(&p, g_metricT); float* dMT  = (float*)p;
    cudaGetSymbolAddress(&p, g_Wqr);     float* dWqr = (float*)p;
    cudaGetSymbolAddress(&p, g_WqmT);    float* dWqm = (float*)p;
    cudaGetSymbolAddress(&p, g_WkT);     float* dWkT = (float*)p;
    cudaGetSymbolAddress(&p, g_WvT);     float* dWvT = (float*)p;
    cudaGetSymbolAddress(&p, g_bqm);     float* dbqm = (float*)p;
    cudaGetSymbolAddress(&p, g_X1);      float* dX1  = (float*)p;
    cudaGetSymbolAddress(&p, g_X2);      float* dX2  = (float*)p;
    cudaGetSymbolAddress(&p, g_Q);       float* dQ   = (float*)p;
    cudaGetSymbolAddress(&p, g_Kt);      float* dK   = (float*)p;
    cudaGetSymbolAddress(&p, g_V);       float* dV   = (float*)p;
    cudaGetSymbolAddress(&p, g_VT);      float* dVT  = (float*)p;
    cudaGetSymbolAddress(&p, g_S);       float* dS   = (float*)p;

    const int M = BATCH * SEQ;                 // 16384
    dim3 blk(NTH), t8(32, 8);

    // pre-round every GEMM operand to tf32 (HW truncates; pre-round keeps rna semantics)
    round4<<<1024, 256>>>((const float4*)X1, (float4*)dX1, (size_t)M * DIM / 4);
    round4<<<1024, 256>>>((const float4*)X2, (float4*)dX2, (size_t)M * DIM / 4);
    round4<<<256, 256>>>((const float4*)Wq, (float4*)dWqr, (size_t)DIM * UDIM / 4);
    transpose_round<<<dim3(32, 32, 1), t8>>>(metric, dMT, DIM, UDIM, 0, 0);
    transpose_round<<<dim3(32, 32, 1), t8>>>(Wk, dWkT, DIM, UDIM, 0, 0);
    transpose_round<<<dim3(32, 32, 1), t8>>>(Wv, dWvT, DIM, UDIM, 0, 0);
    bias_metric<<<UDIM / 256, 256>>>(bq, metric, dbqm);

    // WqmT[v,d] = sum_u metricT[v,u] * Wq[d,u]  ( = (Wq@metric)^T ), rounded
    mma_gemm<<<dim3(DIM / BN_, UDIM / BM_, 1), blk, SMEM_BYTES>>>(
        dMT, dWqr, nullptr, dWqm, DIM, UDIM, UDIM, UDIM, DIM,
        0, 0, 0, 1.f, 1, 0, 0);

    // projections (NT with transposed weights), outputs rounded
    mma_gemm<<<dim3(UDIM / BN_, M / BM_, 1), blk, SMEM_BYTES>>>(
        dX1, dWqm, dbqm, dQ, UDIM, DIM, DIM, DIM, UDIM, 0, 0, 0, 1.f, 1, 0, 0);
    mma_gemm<<<dim3(UDIM / BN_, M / BM_, 1), blk, SMEM_BYTES>>>(
        dX2, dWkT, bk, dK, UDIM, DIM, DIM, DIM, UDIM, 0, 0, 0, 1.f, 1, 0, 0);
    mma_gemm<<<dim3(UDIM / BN_, M / BM_, 1), blk, SMEM_BYTES>>>(
        dX2, dWvT, bv, dV, UDIM, DIM, DIM, DIM, UDIM, 0, 0, 0, 1.f, 1, 0, 0);

    // causal scores (fully-masked tiles early-return; diagonal tiles masked in epilogue)
    mma_gemm<<<dim3(SEQ / BN_, SEQ / BM_, BATCH), blk, SMEM_BYTES>>>(
        dQ, dK, nullptr, dS, SEQ, UDIM, UDIM, UDIM, SEQ,
        (long)SEQ * UDIM, (long)SEQ * UDIM, (long)SEQ * SEQ,
        1.0f / 32.0f, 0, 0, 1);

    softmax_causal<<<dim3(SEQ, BATCH), 256>>>(dS);

    // V^T per batch for the PV NT GEMM
    transpose_round<<<dim3(32, 64, BATCH), t8>>>(dV, dVT, SEQ, UDIM,
        (long)SEQ * UDIM, (long)SEQ * UDIM);

    // O = P @ V  (k-limited by causality at 128 granularity; final output, no rounding)
    mma_gemm<<<dim3(UDIM / BN_, SEQ / BM_, BATCH), blk, SMEM_BYTES>>>(
        dS, dVT, nullptr, out, UDIM, SEQ, SEQ, SEQ, UDIM,
        (long)SEQ * SEQ, (long)SEQ * UDIM, (long)SEQ * UDIM,
        1.f, 0, 1, 0);
}